// round 5
// baseline (speedup 1.0000x reference)
#include <cuda_runtime.h>

#define BB 256
#define TT 2048
#define HH 64
#define NCHUNK (TT / 32)
#define BBTT (BB * TT)

// per-warp-half fc dot partials: [ww][dir][b][t]  (8 MB)
__device__ float g_dotp[2 * 2 * BBTT];

typedef unsigned long long ull;

__device__ __forceinline__ ull pack2(float lo, float hi) {
    ull r; asm("mov.b64 %0, {%1, %2};" : "=l"(r) : "f"(lo), "f"(hi)); return r;
}
__device__ __forceinline__ void unpack2(ull v, float& lo, float& hi) {
    asm("mov.b64 {%0, %1}, %2;" : "=f"(lo), "=f"(hi) : "l"(v));
}
__device__ __forceinline__ ull fma2(ull a, ull b, ull c) {
    ull d; asm("fma.rn.f32x2 %0, %1, %2, %3;" : "=l"(d) : "l"(a), "l"(b), "l"(c)); return d;
}
__device__ __forceinline__ ull add2(ull a, ull b) {
    ull d; asm("add.rn.f32x2 %0, %1, %2;" : "=l"(d) : "l"(a), "l"(b)); return d;
}
__device__ __forceinline__ float tanh_fast(float z) {
    float r; asm("tanh.approx.f32 %0, %1;" : "=f"(r) : "f"(z)); return r;
}

// 128 threads = 4 warps = 2 chains per block; 2 warps cooperate on one chain.
__global__ __launch_bounds__(128, 2) void birnn_main(
    const float* __restrict__ x,
    const float* __restrict__ w_ih_f, const float* __restrict__ w_hh_f,
    const float* __restrict__ b_ih_f, const float* __restrict__ b_hh_f,
    const float* __restrict__ w_ih_b, const float* __restrict__ w_hh_b,
    const float* __restrict__ b_ih_b, const float* __restrict__ b_hh_b,
    const float* __restrict__ w_fc,
    float* __restrict__ out)
{
    // per-chain double-buffered h (plain 64 floats per phase)
    __shared__ __align__(16) float hbuf[2][2][HH];
    __shared__ float pbuf[4][32 * 33];   // per-warp fc-dot partials (padded)

    const int wid  = threadIdx.x >> 5;
    const int lane = threadIdx.x & 31;
    const int cw   = wid >> 1;            // chain within block: 0,1
    const int ww   = wid & 1;             // warp within chain: 0,1
    const int chain = blockIdx.x * 2 + cw;  // 0..511
    const int dir = chain >> 8;             // 0 = fwd, 1 = bwd
    const int b   = chain & 255;
    const int row = ww * 32 + lane;         // the single row this thread owns

    const float* wih = dir ? w_ih_b : w_ih_f;
    const float* whh = dir ? w_hh_b : w_hh_f;
    const float* bih = dir ? b_ih_b : b_ih_f;
    const float* bhh = dir ? b_hh_b : b_hh_f;

    // --- recurrent weight row, k-paired: wr[m] = (W[row][2m], W[row][2m+1]) ---
    ull wr[32];
    {
        const ull* rowp = reinterpret_cast<const ull*>(whh + row * HH);
#pragma unroll
        for (int m = 0; m < 32; m++) wr[m] = rowp[m];
    }
    const float wihR  = wih[row];
    const float biasR = bih[row] + bhh[row];
    const float wfR   = w_fc[row];

    // h = 0 into phase 0 (each warp writes its half)
    hbuf[cw][0][row] = 0.f;
    __syncthreads();

    float h = 0.f;
    const float* xb = x + b * TT;

    // prefetch x for chunk 0
    float xcur = xb[dir ? (TT - 32 + lane) : lane];

    const int barid = cw + 1;

    for (int chunk = 0; chunk < NCHUNK; chunk++) {
        const int tb = dir ? (TT - 1 - chunk * 32) : (chunk * 32);
        int nc = (chunk + 1 < NCHUNK) ? (chunk + 1) : chunk;
        float xnext = xb[dir ? (TT - 1 - nc * 32 - 31 + lane) : (nc * 32 + lane)];

#define STEP(SS, RD, WR)                                                          \
        {                                                                         \
            const int s = (SS);                                                   \
            float xs = __shfl_sync(0xffffffffu, xcur, dir ? (31 - s) : s);        \
            /* fold init (x*w_ih + bias) into accumulator lane 0 */               \
            ull a0 = pack2(fmaf(xs, wihR, biasR), 0.f);                           \
            ull a1 = 0;                                                           \
            const ulonglong2* hr =                                                \
                reinterpret_cast<const ulonglong2*>(&hbuf[cw][RD][0]);            \
            _Pragma("unroll")                                                     \
            for (int k = 0; k < 16; k += 2) {                                     \
                ulonglong2 v = hr[k];                                             \
                ulonglong2 w = hr[k + 1];                                         \
                a0 = fma2(wr[2 * k + 0], v.x, a0);                                \
                a1 = fma2(wr[2 * k + 1], v.y, a1);                                \
                a0 = fma2(wr[2 * k + 2], w.x, a0);                                \
                a1 = fma2(wr[2 * k + 3], w.y, a1);                                \
            }                                                                     \
            ull sA = add2(a0, a1);                                                \
            float lo, hi;                                                         \
            unpack2(sA, lo, hi);                                                  \
            h = tanh_fast(lo + hi);                                               \
            hbuf[cw][WR][row] = h;                                                \
            pbuf[wid][s * 33 + lane] = h * wfR;                                   \
            asm volatile("bar.sync %0, %1;" :: "r"(barid), "n"(64) : "memory");   \
        }

#pragma unroll 1
        for (int s2 = 0; s2 < 16; s2++) {
            STEP(2 * s2,     0, 1)
            STEP(2 * s2 + 1, 1, 0)
        }
#undef STEP

        // transpose-reduce this warp's fc partials: lane l -> half-dot for step l
        // (the bar.sync at the end of step 31 made all pbuf stores visible)
        {
            const float* pr = &pbuf[wid][lane * 33];
            float v[32];
#pragma unroll
            for (int j = 0; j < 32; j++) v[j] = pr[j];
#pragma unroll
            for (int st = 16; st >= 1; st >>= 1)
#pragma unroll
                for (int j = 0; j < 32; j++)
                    if (j < st) v[j] = v[j] + v[j + st];
            int tt = dir ? (tb - lane) : (tb + lane);
            g_dotp[(ww * 2 + dir) * BBTT + b * TT + tt] = v[0];
        }
        xcur = xnext;
    }

    // final hidden state h_n[dir][b][row]
    out[BB * TT + dir * (BB * HH) + b * HH + row] = h;
}

__global__ void birnn_combine(const float* __restrict__ b_fc, float* __restrict__ out)
{
    int i = blockIdx.x * blockDim.x + threadIdx.x;  // 0 .. B*T/4-1
    const float4* f0 = reinterpret_cast<const float4*>(g_dotp + 0 * BBTT); // ww0 fwd
    const float4* b0 = reinterpret_cast<const float4*>(g_dotp + 1 * BBTT); // ww0 bwd
    const float4* f1 = reinterpret_cast<const float4*>(g_dotp + 2 * BBTT); // ww1 fwd
    const float4* b1 = reinterpret_cast<const float4*>(g_dotp + 3 * BBTT); // ww1 bwd
    float4 af = f0[i], bf = f1[i], ab = b0[i], bb = b1[i];
    float bias = b_fc[0];
    float4 o;
    {
        float z, e, r;
        z = 0.5f * ((af.x + bf.x) + (ab.x + bb.x)) + bias;
        asm("ex2.approx.f32 %0, %1;" : "=f"(e) : "f"(-1.4426950408889634f * z));
        asm("rcp.approx.f32 %0, %1;" : "=f"(r) : "f"(1.0f + e));
        o.x = r;
        z = 0.5f * ((af.y + bf.y) + (ab.y + bb.y)) + bias;
        asm("ex2.approx.f32 %0, %1;" : "=f"(e) : "f"(-1.4426950408889634f * z));
        asm("rcp.approx.f32 %0, %1;" : "=f"(r) : "f"(1.0f + e));
        o.y = r;
        z = 0.5f * ((af.z + bf.z) + (ab.z + bb.z)) + bias;
        asm("ex2.approx.f32 %0, %1;" : "=f"(e) : "f"(-1.4426950408889634f * z));
        asm("rcp.approx.f32 %0, %1;" : "=f"(r) : "f"(1.0f + e));
        o.z = r;
        z = 0.5f * ((af.w + bf.w) + (ab.w + bb.w)) + bias;
        asm("ex2.approx.f32 %0, %1;" : "=f"(e) : "f"(-1.4426950408889634f * z));
        asm("rcp.approx.f32 %0, %1;" : "=f"(r) : "f"(1.0f + e));
        o.w = r;
    }
    reinterpret_cast<float4*>(out)[i] = o;
}

extern "C" void kernel_launch(void* const* d_in, const int* in_sizes, int n_in,
                              void* d_out, int out_size)
{
    const float* x      = (const float*)d_in[0];
    const float* w_ih_f = (const float*)d_in[1];
    const float* w_hh_f = (const float*)d_in[2];
    const float* b_ih_f = (const float*)d_in[3];
    const float* b_hh_f = (const float*)d_in[4];
    const float* w_ih_b = (const float*)d_in[5];
    const float* w_hh_b = (const float*)d_in[6];
    const float* b_ih_b = (const float*)d_in[7];
    const float* b_hh_b = (const float*)d_in[8];
    const float* w_fc   = (const float*)d_in[9];
    const float* b_fc   = (const float*)d_in[10];
    float* out = (float*)d_out;

    birnn_main<<<256, 128>>>(x, w_ih_f, w_hh_f, b_ih_f, b_hh_f,
                             w_ih_b, w_hh_b, b_ih_b, b_hh_b, w_fc, out);
    birnn_combine<<<(BB * TT) / 4 / 256, 256>>>(b_fc, out);
}